// round 4
// baseline (speedup 1.0000x reference)
#include <cuda_runtime.h>
#include <math.h>
#include <cstdint>
#include <cstddef>

#define NN    50000
#define NE    800000
#define NG    256
#define D_IN  128
#define D_HID 64
#define D_OUT 128

// ---------------- device scratch (no allocations allowed) ----------------
__device__ int   g_deg[NN];
__device__ int   g_fill[NN];
__device__ int   g_rowptr[NN + 1];
__device__ float g_dinv[NN];
__device__ int   g_src[NE];
__device__ int   g_dst[NE];
__device__ int   g_csrc[NE];
__device__ float g_cnorm[NE];
__device__ __align__(16) float g_bufA[(size_t)NN * 128];
__device__ __align__(16) float g_bufB[(size_t)NN * 128];
__device__ float g_psum[NG * D_OUT];
__device__ int   g_pcnt[NG];
__device__ int   g_idx64;   // 1 if edge_index/batch are int64, 0 if int32

// ---------------- helpers ----------------
__device__ __forceinline__ float gelu_tanh(float x) {
  // jax.nn.gelu default: approximate=True (tanh form)
  float x3 = x * x * x;
  float t  = tanhf(0.7978845608028654f * (x + 0.044715f * x3));
  return 0.5f * x * (1.0f + t);
}

// ---------------- dtype detection (device-side, capture-safe) ----------------
__global__ void detect_kernel(const void* __restrict__ ei, int N) {
  // If underlying data were int32, int64-interpreted values fuse two node ids:
  // v = lo + hi*2^32, hi is a random node index -> almost surely out of [0,N).
  const long long* p = (const long long*)ei;
  int ok = 1;
  for (int i = 0; i < 64; i++) {
    long long v = p[i];
    if (v < 0 || v >= (long long)N) { ok = 0; break; }
  }
  g_idx64 = ok;
}

__device__ __forceinline__ int load_idx(const void* p, long long i) {
  if (g_idx64) return (int)((const long long*)p)[i];
  return ((const int*)p)[i];
}

// ---------------- preprocessing kernels ----------------
__global__ void init_kernel(int n_nodes) {
  int i = blockIdx.x * blockDim.x + threadIdx.x;
  if (i < n_nodes) { g_deg[i] = 0; g_fill[i] = 0; }
  if (i < NG * D_OUT) g_psum[i] = 0.0f;
  if (i < NG) g_pcnt[i] = 0;
}

__global__ void hist_kernel(const void* __restrict__ ei, int E) {
  int e = blockIdx.x * blockDim.x + threadIdx.x;
  if (e >= E) return;
  int s = load_idx(ei, e);
  int d = load_idx(ei, (long long)E + e);
  g_src[e] = s;
  g_dst[e] = d;
  atomicAdd(&g_deg[d], 1);
}

__global__ void dinv_kernel(int N) {
  int n = blockIdx.x * blockDim.x + threadIdx.x;
  if (n >= N) return;
  // self-loop adds +1 to every in-degree; deg >= 1 always
  g_dinv[n] = rsqrtf((float)g_deg[n] + 1.0f);
}

// single-block exclusive scan of g_deg -> g_rowptr
__global__ void scan_kernel(int n) {
  __shared__ int sums[1024];
  int tid   = threadIdx.x;
  int chunk = (n + 1023) >> 10;
  int start = tid * chunk;
  int end   = min(start + chunk, n);
  int s = 0;
  for (int i = start; i < end; i++) s += g_deg[i];
  sums[tid] = s;
  __syncthreads();
  for (int off = 1; off < 1024; off <<= 1) {
    int v = 0;
    if (tid >= off) v = sums[tid - off];
    __syncthreads();
    sums[tid] += v;
    __syncthreads();
  }
  int run = (tid == 0) ? 0 : sums[tid - 1];
  for (int i = start; i < end; i++) {
    g_rowptr[i] = run;
    run += g_deg[i];
  }
  if (end == n && start <= n) g_rowptr[n] = run;
}

__global__ void scatter_kernel(int E) {
  int e = blockIdx.x * blockDim.x + threadIdx.x;
  if (e >= E) return;
  int s = g_src[e];
  int d = g_dst[e];
  int pos = g_rowptr[d] + atomicAdd(&g_fill[d], 1);
  g_csrc[pos]  = s;
  g_cnorm[pos] = g_dinv[s] * g_dinv[d];
}

// ---------------- dense GEMM: H[M,NOUT] = X[M,K] @ W[K,NOUT] ----------------
template <int K, int NOUT>
__global__ void gemm_kernel(const float* __restrict__ X,
                            const float* __restrict__ W,
                            float* __restrict__ H, int M) {
  constexpr int BM = 64;
  constexpr int KB = 32;
  constexpr int TR = 4;          // rows per thread (16 thread-rows)
  constexpr int TC = NOUT / 16;  // cols per thread (4 or 8)
  __shared__ float Xs[BM][KB + 1];
  __shared__ float Ws[KB][NOUT];

  int tid = threadIdx.x;         // 256 threads
  int tx  = tid & 15;
  int ty  = tid >> 4;
  int rb  = blockIdx.x * BM;

  float acc[TR][TC];
#pragma unroll
  for (int i = 0; i < TR; i++)
#pragma unroll
    for (int j = 0; j < TC; j++) acc[i][j] = 0.0f;

  for (int k0 = 0; k0 < K; k0 += KB) {
#pragma unroll
    for (int i = tid; i < BM * KB; i += 256) {
      int r = i / KB, k = i % KB;
      int gr = rb + r;
      Xs[r][k] = (gr < M) ? X[(size_t)gr * K + k0 + k] : 0.0f;
    }
#pragma unroll
    for (int i = tid; i < KB * NOUT; i += 256) {
      int k = i / NOUT, c = i % NOUT;
      Ws[k][c] = W[(size_t)(k0 + k) * NOUT + c];
    }
    __syncthreads();
#pragma unroll
    for (int k = 0; k < KB; k++) {
      float xr[TR], wr[TC];
#pragma unroll
      for (int i = 0; i < TR; i++) xr[i] = Xs[ty * TR + i][k];
#pragma unroll
      for (int j = 0; j < TC; j++) wr[j] = Ws[k][tx * TC + j];
#pragma unroll
      for (int i = 0; i < TR; i++)
#pragma unroll
        for (int j = 0; j < TC; j++) acc[i][j] += xr[i] * wr[j];
    }
    __syncthreads();
  }

#pragma unroll
  for (int i = 0; i < TR; i++) {
    int gr = rb + ty * TR + i;
    if (gr >= M) continue;
    float* hp = H + (size_t)gr * NOUT + tx * TC;
#pragma unroll
    for (int j4 = 0; j4 < TC / 4; j4++) {
      float4 v = make_float4(acc[i][j4 * 4 + 0], acc[i][j4 * 4 + 1],
                             acc[i][j4 * 4 + 2], acc[i][j4 * 4 + 3]);
      reinterpret_cast<float4*>(hp)[j4] = v;
    }
  }
}

// ---------------- CSR aggregation: out[n] = act(self + sum_e norm*h[src] + b) --
template <int V>
__device__ __forceinline__ void loadv(float* d, const float* row, int lane) {
  if constexpr (V == 2) {
    float2 t = __ldg(reinterpret_cast<const float2*>(row) + lane);
    d[0] = t.x; d[1] = t.y;
  } else {
    float4 t = __ldg(reinterpret_cast<const float4*>(row) + lane);
    d[0] = t.x; d[1] = t.y; d[2] = t.z; d[3] = t.w;
  }
}

template <int F, bool ACT>
__global__ void agg_kernel(const float* __restrict__ H,
                           const float* __restrict__ bias,
                           float* __restrict__ out, int N) {
  constexpr int V = F / 32;  // 2 (F=64) or 4 (F=128)
  int t = blockIdx.x * blockDim.x + threadIdx.x;
  int n = t >> 5, lane = t & 31;
  if (n >= N) return;

  float acc[V], tmp[V];
  float dn = g_dinv[n];
  float wself = dn * dn;
  loadv<V>(acc, H + (size_t)n * F, lane);
#pragma unroll
  for (int v = 0; v < V; v++) acc[v] *= wself;

  int e  = g_rowptr[n];
  int e1 = g_rowptr[n + 1];
  for (; e + 1 < e1; e += 2) {
    int s0 = __ldg(&g_csrc[e]);
    int s1 = __ldg(&g_csrc[e + 1]);
    float w0 = __ldg(&g_cnorm[e]);
    float w1 = __ldg(&g_cnorm[e + 1]);
    float a0[V], a1[V];
    loadv<V>(a0, H + (size_t)s0 * F, lane);
    loadv<V>(a1, H + (size_t)s1 * F, lane);
#pragma unroll
    for (int v = 0; v < V; v++) acc[v] += w0 * a0[v];
#pragma unroll
    for (int v = 0; v < V; v++) acc[v] += w1 * a1[v];
  }
  if (e < e1) {
    int s = __ldg(&g_csrc[e]);
    float w = __ldg(&g_cnorm[e]);
    loadv<V>(tmp, H + (size_t)s * F, lane);
#pragma unroll
    for (int v = 0; v < V; v++) acc[v] += w * tmp[v];
  }

#pragma unroll
  for (int v = 0; v < V; v++) {
    float y = acc[v] + __ldg(&bias[lane * V + v]);
    if (ACT) y = gelu_tanh(y);
    acc[v] = y;
  }
  float* op = out + (size_t)n * F;
  if constexpr (V == 2) {
    reinterpret_cast<float2*>(op)[lane] = make_float2(acc[0], acc[1]);
  } else {
    reinterpret_cast<float4*>(op)[lane] = make_float4(acc[0], acc[1], acc[2], acc[3]);
  }
}

// ---------------- global mean pool ----------------
__global__ void pool_kernel(const float* __restrict__ H,
                            const void* __restrict__ batch, int N) {
  int t = blockIdx.x * blockDim.x + threadIdx.x;
  int n = t >> 5, lane = t & 31;
  if (n >= N) return;
  int g = load_idx(batch, n);
  if (g < 0 || g >= NG) return;  // safety
  float4 hv = __ldg(reinterpret_cast<const float4*>(H + (size_t)n * D_OUT) + lane);
  float* p = &g_psum[g * D_OUT + lane * 4];
  atomicAdd(p + 0, hv.x);
  atomicAdd(p + 1, hv.y);
  atomicAdd(p + 2, hv.z);
  atomicAdd(p + 3, hv.w);
  if (lane == 0) atomicAdd(&g_pcnt[g], 1);
}

__global__ void finalize_kernel(float* __restrict__ out, int total) {
  int i = blockIdx.x * blockDim.x + threadIdx.x;
  if (i >= total) return;
  float c = (float)g_pcnt[i >> 7];  // D_OUT == 128
  out[i] = g_psum[i] / fmaxf(c, 1.0f);
}

// ---------------- launch ----------------
extern "C" void kernel_launch(void* const* d_in, const int* in_sizes, int n_in,
                              void* d_out, int out_size) {
  const float* x     = (const float*)d_in[0];
  const void*  ei    = d_in[1];
  const void*  batch = d_in[2];

  // Locate weights robustly: skip any scalar (num_graphs) after batch.
  int wi = 3;
  while (wi < n_in && in_sizes[wi] <= 1) wi++;
  const float* W1 = (const float*)d_in[wi + 0];
  const float* b1 = (const float*)d_in[wi + 1];
  const float* W2 = (const float*)d_in[wi + 2];
  const float* b2 = (const float*)d_in[wi + 3];
  const float* W3 = (const float*)d_in[wi + 4];
  const float* b3 = (const float*)d_in[wi + 5];

  int N = in_sizes[2];          // nodes (batch vector length)
  int E = in_sizes[1] / 2;      // edges (element count / 2, dtype-independent)

  float *bufA, *bufB;
  cudaGetSymbolAddress((void**)&bufA, g_bufA);
  cudaGetSymbolAddress((void**)&bufB, g_bufB);

  const int TB = 256;
  int nb_nodes = (N + TB - 1) / TB;
  int nb_edges = (E + TB - 1) / TB;
  int nb_warp  = (int)(((long long)N * 32 + TB - 1) / TB);
  int nb_gemm  = (N + 63) / 64;

  // ---- preprocessing: dtype detect + CSR + symmetric norm ----
  detect_kernel<<<1, 1>>>(ei, N);
  init_kernel<<<nb_nodes, TB>>>(N);
  hist_kernel<<<nb_edges, TB>>>(ei, E);
  dinv_kernel<<<nb_nodes, TB>>>(N);
  scan_kernel<<<1, 1024>>>(N);
  scatter_kernel<<<nb_edges, TB>>>(E);

  // ---- layer 1: 128 -> 64, gelu ----
  gemm_kernel<D_IN, D_HID><<<nb_gemm, TB>>>(x, W1, bufA, N);
  agg_kernel<D_HID, true><<<nb_warp, TB>>>(bufA, b1, bufB, N);

  // ---- layer 2: 64 -> 64, gelu ----
  gemm_kernel<D_HID, D_HID><<<nb_gemm, TB>>>(bufB, W2, bufA, N);
  agg_kernel<D_HID, true><<<nb_warp, TB>>>(bufA, b2, bufB, N);

  // ---- layer 3: 64 -> 128, no act ----
  gemm_kernel<D_HID, D_OUT><<<nb_gemm, TB>>>(bufB, W3, bufA, N);
  agg_kernel<D_OUT, false><<<nb_warp, TB>>>(bufA, b3, bufB, N);

  // ---- global mean pool ----
  pool_kernel<<<nb_warp, TB>>>(bufB, batch, N);
  int nb_fin = (out_size + TB - 1) / TB;
  finalize_kernel<<<nb_fin, TB>>>((float*)d_out, out_size);
}

// round 5
// speedup vs baseline: 1.0001x; 1.0001x over previous
#include <cuda_runtime.h>
#include <math.h>
#include <cstdint>
#include <cstddef>

#define NN    50000
#define NE    800000
#define NG    256
#define D_IN  128
#define D_HID 64
#define D_OUT 128

// ---------------- device scratch (no allocations allowed) ----------------
__device__ int   g_deg[NN];
__device__ int   g_fill[NN];
__device__ int   g_rowptr[NN + 1];
__device__ float g_dinv[NN];
__device__ int   g_src[NE];
__device__ int   g_dst[NE];
__device__ int   g_csrc[NE];
__device__ float g_cnorm[NE];
__device__ __align__(16) float g_bufA[(size_t)NN * 128];
__device__ __align__(16) float g_bufB[(size_t)NN * 128];
__device__ float g_psum[NG * D_OUT];
__device__ int   g_pcnt[NG];
__device__ int   g_idx64;   // 1 if edge_index/batch are int64, 0 if int32

// ---------------- helpers ----------------
__device__ __forceinline__ float gelu_tanh(float x) {
  // jax.nn.gelu default: approximate=True (tanh form)
  float x3 = x * x * x;
  float t  = tanhf(0.7978845608028654f * (x + 0.044715f * x3));
  return 0.5f * x * (1.0f + t);
}

// ---------------- dtype detection (device-side, capture-safe) ----------------
__global__ void detect_kernel(const void* __restrict__ ei, int N) {
  // If underlying data were int32, int64-interpreted values fuse two node ids:
  // v = lo + hi*2^32, hi is a random node index -> almost surely out of [0,N).
  const long long* p = (const long long*)ei;
  int ok = 1;
  for (int i = 0; i < 64; i++) {
    long long v = p[i];
    if (v < 0 || v >= (long long)N) { ok = 0; break; }
  }
  g_idx64 = ok;
}

__device__ __forceinline__ int load_idx(const void* p, long long i) {
  if (g_idx64) return (int)((const long long*)p)[i];
  return ((const int*)p)[i];
}

// ---------------- preprocessing kernels ----------------
__global__ void init_kernel(int n_nodes) {
  int i = blockIdx.x * blockDim.x + threadIdx.x;
  if (i < n_nodes) { g_deg[i] = 0; g_fill[i] = 0; }
  if (i < NG * D_OUT) g_psum[i] = 0.0f;
  if (i < NG) g_pcnt[i] = 0;
}

__global__ void hist_kernel(const void* __restrict__ ei, int E) {
  int e = blockIdx.x * blockDim.x + threadIdx.x;
  if (e >= E) return;
  int s = load_idx(ei, e);
  int d = load_idx(ei, (long long)E + e);
  g_src[e] = s;
  g_dst[e] = d;
  atomicAdd(&g_deg[d], 1);
}

__global__ void dinv_kernel(int N) {
  int n = blockIdx.x * blockDim.x + threadIdx.x;
  if (n >= N) return;
  // self-loop adds +1 to every in-degree; deg >= 1 always
  g_dinv[n] = rsqrtf((float)g_deg[n] + 1.0f);
}

// single-block exclusive scan of g_deg -> g_rowptr
__global__ void scan_kernel(int n) {
  __shared__ int sums[1024];
  int tid   = threadIdx.x;
  int chunk = (n + 1023) >> 10;
  int start = tid * chunk;
  int end   = min(start + chunk, n);
  int s = 0;
  for (int i = start; i < end; i++) s += g_deg[i];
  sums[tid] = s;
  __syncthreads();
  for (int off = 1; off < 1024; off <<= 1) {
    int v = 0;
    if (tid >= off) v = sums[tid - off];
    __syncthreads();
    sums[tid] += v;
    __syncthreads();
  }
  int run = (tid == 0) ? 0 : sums[tid - 1];
  for (int i = start; i < end; i++) {
    g_rowptr[i] = run;
    run += g_deg[i];
  }
  if (end == n && start <= n) g_rowptr[n] = run;
}

__global__ void scatter_kernel(int E) {
  int e = blockIdx.x * blockDim.x + threadIdx.x;
  if (e >= E) return;
  int s = g_src[e];
  int d = g_dst[e];
  int pos = g_rowptr[d] + atomicAdd(&g_fill[d], 1);
  g_csrc[pos]  = s;
  g_cnorm[pos] = g_dinv[s] * g_dinv[d];
}

// ---------------- dense GEMM: H[M,NOUT] = X[M,K] @ W[K,NOUT] ----------------
template <int K, int NOUT>
__global__ void gemm_kernel(const float* __restrict__ X,
                            const float* __restrict__ W,
                            float* __restrict__ H, int M) {
  constexpr int BM = 64;
  constexpr int KB = 32;
  constexpr int TR = 4;          // rows per thread (16 thread-rows)
  constexpr int TC = NOUT / 16;  // cols per thread (4 or 8)
  __shared__ float Xs[BM][KB + 1];
  __shared__ float Ws[KB][NOUT];

  int tid = threadIdx.x;         // 256 threads
  int tx  = tid & 15;
  int ty  = tid >> 4;
  int rb  = blockIdx.x * BM;

  float acc[TR][TC];
#pragma unroll
  for (int i = 0; i < TR; i++)
#pragma unroll
    for (int j = 0; j < TC; j++) acc[i][j] = 0.0f;

  for (int k0 = 0; k0 < K; k0 += KB) {
#pragma unroll
    for (int i = tid; i < BM * KB; i += 256) {
      int r = i / KB, k = i % KB;
      int gr = rb + r;
      Xs[r][k] = (gr < M) ? X[(size_t)gr * K + k0 + k] : 0.0f;
    }
#pragma unroll
    for (int i = tid; i < KB * NOUT; i += 256) {
      int k = i / NOUT, c = i % NOUT;
      Ws[k][c] = W[(size_t)(k0 + k) * NOUT + c];
    }
    __syncthreads();
#pragma unroll
    for (int k = 0; k < KB; k++) {
      float xr[TR], wr[TC];
#pragma unroll
      for (int i = 0; i < TR; i++) xr[i] = Xs[ty * TR + i][k];
#pragma unroll
      for (int j = 0; j < TC; j++) wr[j] = Ws[k][tx * TC + j];
#pragma unroll
      for (int i = 0; i < TR; i++)
#pragma unroll
        for (int j = 0; j < TC; j++) acc[i][j] += xr[i] * wr[j];
    }
    __syncthreads();
  }

#pragma unroll
  for (int i = 0; i < TR; i++) {
    int gr = rb + ty * TR + i;
    if (gr >= M) continue;
    float* hp = H + (size_t)gr * NOUT + tx * TC;
#pragma unroll
    for (int j4 = 0; j4 < TC / 4; j4++) {
      float4 v = make_float4(acc[i][j4 * 4 + 0], acc[i][j4 * 4 + 1],
                             acc[i][j4 * 4 + 2], acc[i][j4 * 4 + 3]);
      reinterpret_cast<float4*>(hp)[j4] = v;
    }
  }
}

// ---------------- CSR aggregation: out[n] = act(self + sum_e norm*h[src] + b) --
template <int V>
__device__ __forceinline__ void loadv(float* d, const float* row, int lane) {
  if constexpr (V == 2) {
    float2 t = __ldg(reinterpret_cast<const float2*>(row) + lane);
    d[0] = t.x; d[1] = t.y;
  } else {
    float4 t = __ldg(reinterpret_cast<const float4*>(row) + lane);
    d[0] = t.x; d[1] = t.y; d[2] = t.z; d[3] = t.w;
  }
}

template <int F, bool ACT>
__global__ void agg_kernel(const float* __restrict__ H,
                           const float* __restrict__ bias,
                           float* __restrict__ out, int N) {
  constexpr int V = F / 32;  // 2 (F=64) or 4 (F=128)
  int t = blockIdx.x * blockDim.x + threadIdx.x;
  int n = t >> 5, lane = t & 31;
  if (n >= N) return;

  float acc[V], tmp[V];
  float dn = g_dinv[n];
  float wself = dn * dn;
  loadv<V>(acc, H + (size_t)n * F, lane);
#pragma unroll
  for (int v = 0; v < V; v++) acc[v] *= wself;

  int e  = g_rowptr[n];
  int e1 = g_rowptr[n + 1];
  for (; e + 1 < e1; e += 2) {
    int s0 = __ldg(&g_csrc[e]);
    int s1 = __ldg(&g_csrc[e + 1]);
    float w0 = __ldg(&g_cnorm[e]);
    float w1 = __ldg(&g_cnorm[e + 1]);
    float a0[V], a1[V];
    loadv<V>(a0, H + (size_t)s0 * F, lane);
    loadv<V>(a1, H + (size_t)s1 * F, lane);
#pragma unroll
    for (int v = 0; v < V; v++) acc[v] += w0 * a0[v];
#pragma unroll
    for (int v = 0; v < V; v++) acc[v] += w1 * a1[v];
  }
  if (e < e1) {
    int s = __ldg(&g_csrc[e]);
    float w = __ldg(&g_cnorm[e]);
    loadv<V>(tmp, H + (size_t)s * F, lane);
#pragma unroll
    for (int v = 0; v < V; v++) acc[v] += w * tmp[v];
  }

#pragma unroll
  for (int v = 0; v < V; v++) {
    float y = acc[v] + __ldg(&bias[lane * V + v]);
    if (ACT) y = gelu_tanh(y);
    acc[v] = y;
  }
  float* op = out + (size_t)n * F;
  if constexpr (V == 2) {
    reinterpret_cast<float2*>(op)[lane] = make_float2(acc[0], acc[1]);
  } else {
    reinterpret_cast<float4*>(op)[lane] = make_float4(acc[0], acc[1], acc[2], acc[3]);
  }
}

// ---------------- global mean pool ----------------
__global__ void pool_kernel(const float* __restrict__ H,
                            const void* __restrict__ batch, int N) {
  int t = blockIdx.x * blockDim.x + threadIdx.x;
  int n = t >> 5, lane = t & 31;
  if (n >= N) return;
  int g = load_idx(batch, n);
  if (g < 0 || g >= NG) return;  // safety
  float4 hv = __ldg(reinterpret_cast<const float4*>(H + (size_t)n * D_OUT) + lane);
  float* p = &g_psum[g * D_OUT + lane * 4];
  atomicAdd(p + 0, hv.x);
  atomicAdd(p + 1, hv.y);
  atomicAdd(p + 2, hv.z);
  atomicAdd(p + 3, hv.w);
  if (lane == 0) atomicAdd(&g_pcnt[g], 1);
}

__global__ void finalize_kernel(float* __restrict__ out, int total) {
  int i = blockIdx.x * blockDim.x + threadIdx.x;
  if (i >= total) return;
  float c = (float)g_pcnt[i >> 7];  // D_OUT == 128
  out[i] = g_psum[i] / fmaxf(c, 1.0f);
}

// ---------------- launch ----------------
extern "C" void kernel_launch(void* const* d_in, const int* in_sizes, int n_in,
                              void* d_out, int out_size) {
  const float* x     = (const float*)d_in[0];
  const void*  ei    = d_in[1];
  const void*  batch = d_in[2];

  // Locate weights robustly: skip any scalar (num_graphs) after batch.
  int wi = 3;
  while (wi < n_in && in_sizes[wi] <= 1) wi++;
  const float* W1 = (const float*)d_in[wi + 0];
  const float* b1 = (const float*)d_in[wi + 1];
  const float* W2 = (const float*)d_in[wi + 2];
  const float* b2 = (const float*)d_in[wi + 3];
  const float* W3 = (const float*)d_in[wi + 4];
  const float* b3 = (const float*)d_in[wi + 5];

  int N = in_sizes[2];          // nodes (batch vector length)
  int E = in_sizes[1] / 2;      // edges (element count / 2, dtype-independent)

  float *bufA, *bufB;
  cudaGetSymbolAddress((void**)&bufA, g_bufA);
  cudaGetSymbolAddress((void**)&bufB, g_bufB);

  const int TB = 256;
  int nb_nodes = (N + TB - 1) / TB;
  int nb_edges = (E + TB - 1) / TB;
  int nb_warp  = (int)(((long long)N * 32 + TB - 1) / TB);
  int nb_gemm  = (N + 63) / 64;

  // ---- preprocessing: dtype detect + CSR + symmetric norm ----
  detect_kernel<<<1, 1>>>(ei, N);
  init_kernel<<<nb_nodes, TB>>>(N);
  hist_kernel<<<nb_edges, TB>>>(ei, E);
  dinv_kernel<<<nb_nodes, TB>>>(N);
  scan_kernel<<<1, 1024>>>(N);
  scatter_kernel<<<nb_edges, TB>>>(E);

  // ---- layer 1: 128 -> 64, gelu ----
  gemm_kernel<D_IN, D_HID><<<nb_gemm, TB>>>(x, W1, bufA, N);
  agg_kernel<D_HID, true><<<nb_warp, TB>>>(bufA, b1, bufB, N);

  // ---- layer 2: 64 -> 64, gelu ----
  gemm_kernel<D_HID, D_HID><<<nb_gemm, TB>>>(bufB, W2, bufA, N);
  agg_kernel<D_HID, true><<<nb_warp, TB>>>(bufA, b2, bufB, N);

  // ---- layer 3: 64 -> 128, no act ----
  gemm_kernel<D_HID, D_OUT><<<nb_gemm, TB>>>(bufB, W3, bufA, N);
  agg_kernel<D_OUT, false><<<nb_warp, TB>>>(bufA, b3, bufB, N);

  // ---- global mean pool ----
  pool_kernel<<<nb_warp, TB>>>(bufB, batch, N);
  int nb_fin = (out_size + TB - 1) / TB;
  finalize_kernel<<<nb_fin, TB>>>((float*)d_out, out_size);
}

// round 6
// speedup vs baseline: 1.2646x; 1.2645x over previous
#include <cuda_runtime.h>
#include <math.h>
#include <cstdint>
#include <cstddef>

#define NN    50000
#define NE    800000
#define NG    256
#define D_IN  128
#define D_HID 64
#define D_OUT 128

// ---------------- device scratch (no allocations allowed) ----------------
__device__ int   g_deg[NN];
__device__ int   g_fill[NN];
__device__ int   g_rowptr[NN + 1];
__device__ float g_dinv[NN];
__device__ int   g_src[NE];
__device__ int   g_dst[NE];
__device__ int   g_csrc[NE];
__device__ float g_cnorm[NE];
__device__ __align__(16) float g_bufA[(size_t)NN * D_HID];
__device__ __align__(16) float g_bufB[(size_t)NN * D_HID];
__device__ float g_psum[NG * D_HID];
__device__ int   g_pcnt[NG];
__device__ int   g_idx64;   // 1 if edge_index/batch are int64, 0 if int32

// ---------------- helpers ----------------
__device__ __forceinline__ float gelu_tanh(float x) {
  float x3 = x * x * x;
  float t  = tanhf(0.7978845608028654f * (x + 0.044715f * x3));
  return 0.5f * x * (1.0f + t);
}

__device__ __forceinline__ int load_idx(const void* p, long long i) {
  if (g_idx64) return (int)((const long long*)p)[i];
  return ((const int*)p)[i];
}

// ---------------- init + dtype detect (fused) ----------------
__global__ void init_kernel(const void* __restrict__ ei, int n_nodes, int N) {
  int i = blockIdx.x * blockDim.x + threadIdx.x;
  if (i == 0) {
    // int32 data read as int64 fuses two random node ids -> out of [0,N) a.s.
    const long long* p = (const long long*)ei;
    int ok = 1;
    for (int k = 0; k < 64; k++) {
      long long v = p[k];
      if (v < 0 || v >= (long long)N) { ok = 0; break; }
    }
    g_idx64 = ok;
  }
  if (i < n_nodes) { g_deg[i] = 0; g_fill[i] = 0; }
  if (i < NG * D_HID) g_psum[i] = 0.0f;
  if (i < NG) g_pcnt[i] = 0;
}

__global__ void hist_kernel(const void* __restrict__ ei, int E) {
  int e = blockIdx.x * blockDim.x + threadIdx.x;
  if (e >= E) return;
  int s = load_idx(ei, e);
  int d = load_idx(ei, (long long)E + e);
  g_src[e] = s;
  g_dst[e] = d;
  atomicAdd(&g_deg[d], 1);
}

// single-block exclusive scan of g_deg -> g_rowptr, fused dinv computation
__global__ void scan_kernel(int n) {
  __shared__ int sums[1024];
  int tid   = threadIdx.x;
  int chunk = (n + 1023) >> 10;
  int start = tid * chunk;
  int end   = min(start + chunk, n);
  int s = 0;
  for (int i = start; i < end; i++) s += g_deg[i];
  sums[tid] = s;
  __syncthreads();
  for (int off = 1; off < 1024; off <<= 1) {
    int v = 0;
    if (tid >= off) v = sums[tid - off];
    __syncthreads();
    sums[tid] += v;
    __syncthreads();
  }
  int run = (tid == 0) ? 0 : sums[tid - 1];
  for (int i = start; i < end; i++) {
    int d = g_deg[i];
    g_rowptr[i] = run;
    g_dinv[i]   = rsqrtf((float)d + 1.0f);   // self-loop: deg+1
    run += d;
  }
  if (end == n) g_rowptr[n] = run;
}

__global__ void scatter_kernel(int E) {
  int e = blockIdx.x * blockDim.x + threadIdx.x;
  if (e >= E) return;
  int s = g_src[e];
  int d = g_dst[e];
  int pos = g_rowptr[d] + atomicAdd(&g_fill[d], 1);
  g_csrc[pos]  = s;
  g_cnorm[pos] = g_dinv[s] * g_dinv[d];
}

// ---------------- dense GEMM: H[M,64] = X[M,K] @ W[K,64] ------------------
// BM=128, KB=32, 256 threads, 8x4 register tile. Inner loop is float4/broadcast
// smem reads -> FFMA-bound.
template <int K>
__global__ void gemm_kernel(const float* __restrict__ X,
                            const float* __restrict__ W,
                            float* __restrict__ H, int M) {
  constexpr int NOUT = D_HID;
  constexpr int BM = 128;
  constexpr int KB = 32;
  constexpr int TR = 8;          // rows per thread   (16 thread-rows * 8)
  constexpr int TC = 4;          // cols per thread   (16 thread-cols * 4)
  constexpr int XS = BM + 4;     // stride mult of 4 floats (16B-aligned rows)
  __shared__ float Xs[KB][XS];   // transposed: Xs[k][r]
  __shared__ float Ws[KB][NOUT];

  int tid = threadIdx.x;         // 256 threads
  int tx  = tid & 15;
  int ty  = tid >> 4;
  int rb  = blockIdx.x * BM;

  float acc[TR][TC];
#pragma unroll
  for (int i = 0; i < TR; i++)
#pragma unroll
    for (int j = 0; j < TC; j++) acc[i][j] = 0.0f;

  for (int k0 = 0; k0 < K; k0 += KB) {
    // X tile: global-coalesced along k, write transposed
#pragma unroll
    for (int i = tid; i < BM * KB; i += 256) {
      int r = i / KB, k = i % KB;
      int gr = rb + r;
      Xs[k][r] = (gr < M) ? X[(size_t)gr * K + k0 + k] : 0.0f;
    }
#pragma unroll
    for (int i = tid; i < KB * NOUT; i += 256) {
      int k = i / NOUT, c = i % NOUT;
      Ws[k][c] = W[(size_t)(k0 + k) * NOUT + c];
    }
    __syncthreads();
#pragma unroll
    for (int k = 0; k < KB; k++) {
      float4 x0 = *reinterpret_cast<const float4*>(&Xs[k][ty * TR]);
      float4 x1 = *reinterpret_cast<const float4*>(&Xs[k][ty * TR + 4]);
      float4 w  = *reinterpret_cast<const float4*>(&Ws[k][tx * TC]);
      float xr[TR] = {x0.x, x0.y, x0.z, x0.w, x1.x, x1.y, x1.z, x1.w};
      float wr[TC] = {w.x, w.y, w.z, w.w};
#pragma unroll
      for (int i = 0; i < TR; i++)
#pragma unroll
        for (int j = 0; j < TC; j++) acc[i][j] += xr[i] * wr[j];
    }
    __syncthreads();
  }

#pragma unroll
  for (int i = 0; i < TR; i++) {
    int gr = rb + ty * TR + i;
    if (gr >= M) continue;
    float4 v = make_float4(acc[i][0], acc[i][1], acc[i][2], acc[i][3]);
    *reinterpret_cast<float4*>(H + (size_t)gr * NOUT + tx * TC) = v;
  }
}

// ------- CSR aggregation (F=64): out[n] = gelu(self + sum norm*h[src] + b) ----
template <bool ACT>
__global__ void agg_kernel(const float* __restrict__ H,
                           const float* __restrict__ bias,
                           float* __restrict__ out, int N) {
  int t = blockIdx.x * blockDim.x + threadIdx.x;
  int n = t >> 5, lane = t & 31;
  if (n >= N) return;

  float dn = g_dinv[n];
  float wself = dn * dn;
  float2 self = __ldg(reinterpret_cast<const float2*>(H + (size_t)n * D_HID) + lane);
  float a0 = self.x * wself, a1 = self.y * wself;

  int e  = g_rowptr[n];
  int e1 = g_rowptr[n + 1];
  for (; e + 1 < e1; e += 2) {
    int   s0 = __ldg(&g_csrc[e]);
    int   s1 = __ldg(&g_csrc[e + 1]);
    float w0 = __ldg(&g_cnorm[e]);
    float w1 = __ldg(&g_cnorm[e + 1]);
    float2 h0 = __ldg(reinterpret_cast<const float2*>(H + (size_t)s0 * D_HID) + lane);
    float2 h1 = __ldg(reinterpret_cast<const float2*>(H + (size_t)s1 * D_HID) + lane);
    a0 += w0 * h0.x; a1 += w0 * h0.y;
    a0 += w1 * h1.x; a1 += w1 * h1.y;
  }
  if (e < e1) {
    int   s = __ldg(&g_csrc[e]);
    float w = __ldg(&g_cnorm[e]);
    float2 h = __ldg(reinterpret_cast<const float2*>(H + (size_t)s * D_HID) + lane);
    a0 += w * h.x; a1 += w * h.y;
  }

  float y0 = a0 + __ldg(&bias[lane * 2]);
  float y1 = a1 + __ldg(&bias[lane * 2 + 1]);
  if (ACT) { y0 = gelu_tanh(y0); y1 = gelu_tanh(y1); }
  reinterpret_cast<float2*>(out + (size_t)n * D_HID)[lane] = make_float2(y0, y1);
}

// ------- layer-3 aggregation fused with mean-pool accumulation (no bias) ----
__global__ void agg_pool_kernel(const float* __restrict__ H,
                                const void* __restrict__ batch, int N) {
  int t = blockIdx.x * blockDim.x + threadIdx.x;
  int n = t >> 5, lane = t & 31;
  if (n >= N) return;

  float dn = g_dinv[n];
  float wself = dn * dn;
  float2 self = __ldg(reinterpret_cast<const float2*>(H + (size_t)n * D_HID) + lane);
  float a0 = self.x * wself, a1 = self.y * wself;

  int e  = g_rowptr[n];
  int e1 = g_rowptr[n + 1];
  for (; e + 1 < e1; e += 2) {
    int   s0 = __ldg(&g_csrc[e]);
    int   s1 = __ldg(&g_csrc[e + 1]);
    float w0 = __ldg(&g_cnorm[e]);
    float w1 = __ldg(&g_cnorm[e + 1]);
    float2 h0 = __ldg(reinterpret_cast<const float2*>(H + (size_t)s0 * D_HID) + lane);
    float2 h1 = __ldg(reinterpret_cast<const float2*>(H + (size_t)s1 * D_HID) + lane);
    a0 += w0 * h0.x; a1 += w0 * h0.y;
    a0 += w1 * h1.x; a1 += w1 * h1.y;
  }
  if (e < e1) {
    int   s = __ldg(&g_csrc[e]);
    float w = __ldg(&g_cnorm[e]);
    float2 h = __ldg(reinterpret_cast<const float2*>(H + (size_t)s * D_HID) + lane);
    a0 += w * h.x; a1 += w * h.y;
  }

  int g = load_idx(batch, n);
  float* p = &g_psum[g * D_HID + lane * 2];
  atomicAdd(p, a0);
  atomicAdd(p + 1, a1);
  if (lane == 0) atomicAdd(&g_pcnt[g], 1);
}

// ------- final tiny GEMM: out[g,:] = mean_g @ W3 + b3 -----------------------
__global__ void final_gemm_kernel(const float* __restrict__ W3,
                                  const float* __restrict__ b3,
                                  float* __restrict__ out) {
  int g = blockIdx.x;
  int j = threadIdx.x;  // 128 threads = D_OUT
  __shared__ float row[D_HID];
  int cnt = g_pcnt[g];
  float inv = (cnt > 0) ? (1.0f / (float)cnt) : 0.0f;
  if (j < D_HID) row[j] = g_psum[g * D_HID + j] * inv;
  __syncthreads();
  float acc = (cnt > 0) ? __ldg(&b3[j]) : 0.0f;
#pragma unroll 8
  for (int k = 0; k < D_HID; k++) acc += row[k] * __ldg(&W3[k * D_OUT + j]);
  out[(size_t)g * D_OUT + j] = acc;
}

// ---------------- launch ----------------
extern "C" void kernel_launch(void* const* d_in, const int* in_sizes, int n_in,
                              void* d_out, int out_size) {
  const float* x     = (const float*)d_in[0];
  const void*  ei    = d_in[1];
  const void*  batch = d_in[2];

  // Locate weights robustly: skip any scalar (num_graphs) after batch.
  int wi = 3;
  while (wi < n_in && in_sizes[wi] <= 1) wi++;
  const float* W1 = (const float*)d_in[wi + 0];
  const float* b1 = (const float*)d_in[wi + 1];
  const float* W2 = (const float*)d_in[wi + 2];
  const float* b2 = (const float*)d_in[wi + 3];
  const float* W3 = (const float*)d_in[wi + 4];
  const float* b3 = (const float*)d_in[wi + 5];

  int N = in_sizes[2];          // nodes (batch vector length)
  int E = in_sizes[1] / 2;      // edges

  float *bufA, *bufB;
  cudaGetSymbolAddress((void**)&bufA, g_bufA);
  cudaGetSymbolAddress((void**)&bufB, g_bufB);

  const int TB = 256;
  int nb_nodes = (N + TB - 1) / TB;
  int nb_edges = (E + TB - 1) / TB;
  int nb_warp  = (int)(((long long)N * 32 + TB - 1) / TB);
  int nb_gemm  = (N + 127) / 128;

  // ---- preprocessing: CSR + symmetric norm (4 launches) ----
  init_kernel<<<nb_nodes, TB>>>(ei, N, N);
  hist_kernel<<<nb_edges, TB>>>(ei, E);
  scan_kernel<<<1, 1024>>>(N);
  scatter_kernel<<<nb_edges, TB>>>(E);

  // ---- layer 1: GEMM 128->64, agg + gelu ----
  gemm_kernel<D_IN><<<nb_gemm, TB>>>(x, W1, bufA, N);
  agg_kernel<true><<<nb_warp, TB>>>(bufA, b1, bufB, N);

  // ---- layer 2: GEMM 64->64, agg + gelu ----
  gemm_kernel<D_HID><<<nb_gemm, TB>>>(bufB, W2, bufA, N);
  agg_kernel<true><<<nb_warp, TB>>>(bufA, b2, bufB, N);

  // ---- layer 3 (reordered): agg in 64-dim fused with mean-pool, then
  //      tiny [NG,64]@[64,128] GEMM + b3.  Valid since agg & pool are linear.
  agg_pool_kernel<<<nb_warp, TB>>>(bufB, batch, N);
  final_gemm_kernel<<<out_size / D_OUT, D_OUT>>>(W3, b3, (float*)d_out);
}